// round 14
// baseline (speedup 1.0000x reference)
#include <cuda_runtime.h>
#include <cuda_bf16.h>

// Upsample2d (up=2, binomial 4-tap) == separable interp:
//   out[2m]   = 0.25*x[m-1] + 0.75*x[m]
//   out[2m+1] = 0.75*x[m]   + 0.25*x[m+1]
// R14: R11 verbatim (RPW=8 front-batched loads, warp = full input row,
// 256-bit stores, grid 2048) with ONE change: stores use default write-back
// policy instead of .cs (streaming). Tests whether evict-first dirty lines
// were hurting DRAM write-burst locality.

#define W_IN  128
#define H_IN  128
#define W_OUT 256
#define H_OUT 256
#define WARPS 8
#define RPW   8      // input rows per warp strip
// block covers WARPS*RPW = 64 input rows -> 2 blocks per image

__device__ __forceinline__ void compute_h(float4 a, int lane, float* __restrict__ h) {
    float left  = __shfl_up_sync(0xffffffffu, a.w, 1);
    float right = __shfl_down_sync(0xffffffffu, a.x, 1);
    if (lane == 0)  left  = 0.0f;
    if (lane == 31) right = 0.0f;
    h[0] = 0.25f * left + 0.75f * a.x;
    h[1] = 0.75f * a.x  + 0.25f * a.y;
    h[2] = 0.25f * a.x  + 0.75f * a.y;
    h[3] = 0.75f * a.y  + 0.25f * a.z;
    h[4] = 0.25f * a.y  + 0.75f * a.z;
    h[5] = 0.75f * a.z  + 0.25f * a.w;
    h[6] = 0.25f * a.z  + 0.75f * a.w;
    h[7] = 0.75f * a.w  + 0.25f * right;
}

__device__ __forceinline__ void store_row_v8(float* p,
                                             const float* __restrict__ w0,
                                             const float* __restrict__ w1,
                                             float c0, float c1) {
    float o0 = c0 * w0[0] + c1 * w1[0];
    float o1 = c0 * w0[1] + c1 * w1[1];
    float o2 = c0 * w0[2] + c1 * w1[2];
    float o3 = c0 * w0[3] + c1 * w1[3];
    float o4 = c0 * w0[4] + c1 * w1[4];
    float o5 = c0 * w0[5] + c1 * w1[5];
    float o6 = c0 * w0[6] + c1 * w1[6];
    float o7 = c0 * w0[7] + c1 * w1[7];
    asm volatile("st.global.v8.f32 [%0], {%1,%2,%3,%4,%5,%6,%7,%8};"
                 :: "l"(p), "f"(o0), "f"(o1), "f"(o2), "f"(o3),
                    "f"(o4), "f"(o5), "f"(o6), "f"(o7)
                 : "memory");
}

__global__ __launch_bounds__(WARPS * 32)
void Upsample_63797444215162_kernel(const float* __restrict__ x,
                                    float* __restrict__ out) {
    const int tid  = threadIdx.x;
    const int warp = tid >> 5;
    const int lane = tid & 31;
    const int img  = blockIdx.x >> 1;           // 2 blocks per image
    const int half = blockIdx.x & 1;

    const float* __restrict__ xi = x   + (size_t)img * (H_IN * W_IN);
    float*       __restrict__ oi = out + (size_t)img * (H_OUT * W_OUT);

    const int r0 = half * (WARPS * RPW) + warp * RPW;   // strip start row
    const int c0 = lane * 4;                            // input col base
    const int oc = lane * 8;                            // output col base

    // Front-batched loads: halo row (r0-1, clamped) + RPW body rows, all
    // issued back-to-back. For r0==0 the clamped load's value is discarded
    // (hp forced to zero below).
    const int rh = (r0 == 0) ? 0 : (r0 - 1);
    float4 vh;
    float4 v[RPW];
    {
        vh = *reinterpret_cast<const float4*>(xi + rh * W_IN + c0);
        #pragma unroll
        for (int k = 0; k < RPW; ++k)
            v[k] = *reinterpret_cast<const float4*>(xi + (r0 + k) * W_IN + c0);
    }

    float hp[8];                                        // h(n-1), rolled
    if (r0 == 0) {
        #pragma unroll
        for (int j = 0; j < 8; ++j) hp[j] = 0.0f;
    } else {
        compute_h(vh, lane, hp);
    }

    #pragma unroll
    for (int k = 0; k < RPW; ++k) {
        const int n = r0 + k;
        float h[8];
        compute_h(v[k], lane, h);

        // out row 2n-1 = 0.75*h(n-1) + 0.25*h(n)   (row -1 doesn't exist)
        if (n > 0)
            store_row_v8(oi + (2 * n - 1) * W_OUT + oc, hp, h, 0.75f, 0.25f);
        // out row 2n   = 0.25*h(n-1) + 0.75*h(n)
        store_row_v8(oi + (2 * n) * W_OUT + oc, hp, h, 0.25f, 0.75f);

        #pragma unroll
        for (int j = 0; j < 8; ++j) hp[j] = h[j];
    }

    // last output row 2H-1 = 0.75*h(H-1), owned by the last strip
    if (r0 + RPW == H_IN) {
        float z[8] = {0, 0, 0, 0, 0, 0, 0, 0};
        store_row_v8(oi + (H_OUT - 1) * W_OUT + oc, hp, z, 0.75f, 0.0f);
    }
}

extern "C" void kernel_launch(void* const* d_in, const int* in_sizes, int n_in,
                              void* d_out, int out_size) {
    const float* x = (const float*)d_in[0];   // [8,128,128,128] fp32
    // d_in[1] is the fixed 4x4 binomial kernel; weights folded into code.
    float* out = (float*)d_out;               // [8,128,256,256] fp32

    const int n_img = in_sizes[0] / (H_IN * W_IN);   // B*C = 1024
    Upsample_63797444215162_kernel<<<n_img * 2, WARPS * 32>>>(x, out);
}

// round 15
// speedup vs baseline: 1.0029x; 1.0029x over previous
#include <cuda_runtime.h>
#include <cuda_bf16.h>

// Upsample2d (up=2, binomial 4-tap) == separable interp:
//   out[2m]   = 0.25*x[m-1] + 0.75*x[m]
//   out[2m+1] = 0.75*x[m]   + 0.25*x[m+1]
// R15: champion R11 (RPW=8 front-batched loads, warp = full input row,
// 256-bit .cs stores, grid 2048) with ONE change: the store asm drops its
// "memory" clobber (kept volatile), letting ptxas interleave independent
// FMAs/SHFLs across store issue instead of fencing each store.

#define W_IN  128
#define H_IN  128
#define W_OUT 256
#define H_OUT 256
#define WARPS 8
#define RPW   8      // input rows per warp strip
// block covers WARPS*RPW = 64 input rows -> 2 blocks per image

__device__ __forceinline__ void compute_h(float4 a, int lane, float* __restrict__ h) {
    float left  = __shfl_up_sync(0xffffffffu, a.w, 1);
    float right = __shfl_down_sync(0xffffffffu, a.x, 1);
    if (lane == 0)  left  = 0.0f;
    if (lane == 31) right = 0.0f;
    h[0] = 0.25f * left + 0.75f * a.x;
    h[1] = 0.75f * a.x  + 0.25f * a.y;
    h[2] = 0.25f * a.x  + 0.75f * a.y;
    h[3] = 0.75f * a.y  + 0.25f * a.z;
    h[4] = 0.25f * a.y  + 0.75f * a.z;
    h[5] = 0.75f * a.z  + 0.25f * a.w;
    h[6] = 0.25f * a.z  + 0.75f * a.w;
    h[7] = 0.75f * a.w  + 0.25f * right;
}

// volatile (must issue) but NO "memory" clobber: all inputs arrive via
// registers, the output buffer is never read by this kernel, and stores go to
// disjoint addresses — no ordering constraint is needed.
__device__ __forceinline__ void store_row_v8(float* p,
                                             const float* __restrict__ w0,
                                             const float* __restrict__ w1,
                                             float c0, float c1) {
    float o0 = c0 * w0[0] + c1 * w1[0];
    float o1 = c0 * w0[1] + c1 * w1[1];
    float o2 = c0 * w0[2] + c1 * w1[2];
    float o3 = c0 * w0[3] + c1 * w1[3];
    float o4 = c0 * w0[4] + c1 * w1[4];
    float o5 = c0 * w0[5] + c1 * w1[5];
    float o6 = c0 * w0[6] + c1 * w1[6];
    float o7 = c0 * w0[7] + c1 * w1[7];
    asm volatile("st.global.cs.v8.f32 [%0], {%1,%2,%3,%4,%5,%6,%7,%8};"
                 :: "l"(p), "f"(o0), "f"(o1), "f"(o2), "f"(o3),
                    "f"(o4), "f"(o5), "f"(o6), "f"(o7));
}

__global__ __launch_bounds__(WARPS * 32)
void Upsample_63797444215162_kernel(const float* __restrict__ x,
                                    float* __restrict__ out) {
    const int tid  = threadIdx.x;
    const int warp = tid >> 5;
    const int lane = tid & 31;
    const int img  = blockIdx.x >> 1;           // 2 blocks per image
    const int half = blockIdx.x & 1;

    const float* __restrict__ xi = x   + (size_t)img * (H_IN * W_IN);
    float*       __restrict__ oi = out + (size_t)img * (H_OUT * W_OUT);

    const int r0 = half * (WARPS * RPW) + warp * RPW;   // strip start row
    const int c0 = lane * 4;                            // input col base
    const int oc = lane * 8;                            // output col base

    // Front-batched loads: halo row (r0-1, clamped) + RPW body rows, all
    // issued back-to-back. For r0==0 the clamped load's value is discarded
    // (hp forced to zero below).
    const int rh = (r0 == 0) ? 0 : (r0 - 1);
    float4 vh;
    float4 v[RPW];
    {
        vh = *reinterpret_cast<const float4*>(xi + rh * W_IN + c0);
        #pragma unroll
        for (int k = 0; k < RPW; ++k)
            v[k] = *reinterpret_cast<const float4*>(xi + (r0 + k) * W_IN + c0);
    }

    float hp[8];                                        // h(n-1), rolled
    if (r0 == 0) {
        #pragma unroll
        for (int j = 0; j < 8; ++j) hp[j] = 0.0f;
    } else {
        compute_h(vh, lane, hp);
    }

    #pragma unroll
    for (int k = 0; k < RPW; ++k) {
        const int n = r0 + k;
        float h[8];
        compute_h(v[k], lane, h);

        // out row 2n-1 = 0.75*h(n-1) + 0.25*h(n)   (row -1 doesn't exist)
        if (n > 0)
            store_row_v8(oi + (2 * n - 1) * W_OUT + oc, hp, h, 0.75f, 0.25f);
        // out row 2n   = 0.25*h(n-1) + 0.75*h(n)
        store_row_v8(oi + (2 * n) * W_OUT + oc, hp, h, 0.25f, 0.75f);

        #pragma unroll
        for (int j = 0; j < 8; ++j) hp[j] = h[j];
    }

    // last output row 2H-1 = 0.75*h(H-1), owned by the last strip
    if (r0 + RPW == H_IN) {
        float z[8] = {0, 0, 0, 0, 0, 0, 0, 0};
        store_row_v8(oi + (H_OUT - 1) * W_OUT + oc, hp, z, 0.75f, 0.0f);
    }
}

extern "C" void kernel_launch(void* const* d_in, const int* in_sizes, int n_in,
                              void* d_out, int out_size) {
    const float* x = (const float*)d_in[0];   // [8,128,128,128] fp32
    // d_in[1] is the fixed 4x4 binomial kernel; weights folded into code.
    float* out = (float*)d_out;               // [8,128,256,256] fp32

    const int n_img = in_sizes[0] / (H_IN * W_IN);   // B*C = 1024
    Upsample_63797444215162_kernel<<<n_img * 2, WARPS * 32>>>(x, out);
}